// round 1
// baseline (speedup 1.0000x reference)
#include <cuda_runtime.h>
#include <cuda_bf16.h>
#include <math.h>

// ---------------- problem constants ----------------
#define BB 64
#define TT 256
#define EE 300
#define EP 304          // padded E
#define HH 256
#define G4H 1024        // 4*H
#define INTER 128
#define NUM_LABELS 17
#define TL 19           // TOTAL_LABELS
#define START_IDX 17
#define END_IDX 18
#define LOW_POT -10000.0f

#define MTOT (BB*TT)            // 16384, m = t*64 + b
#define NB_LSTM 128             // persistent blocks (<=148 SMs -> co-resident)

// ---------------- scratch (device globals; allocation-free rule) ----------------
__device__ float g_emb[MTOT * EP];            // [m][304]
__device__ float g_xproj[(size_t)MTOT * 2048];// [t][b][dir*1024 + g*256 + u]
__device__ float g_hcat[(size_t)MTOT * 512];  // [t][b][dir*256 + u]
__device__ float g_unary[BB * TT * TL];       // [b][t][l]
__device__ unsigned g_cnt;                    // grid barrier
__device__ unsigned g_sense;

// ---------------- embedding gather ----------------
__global__ void k_embed(const int* __restrict__ x, const float* __restrict__ tbl) {
    int idx = blockIdx.x * 256 + threadIdx.x;
    if (idx >= MTOT * EP) return;
    int m = idx / EP, e = idx - m * EP;
    int bat = m & 63, t = m >> 6;
    int tok = x[bat * TT + t];
    g_emb[idx] = (e < EE) ? tbl[(size_t)tok * EE + e] : 0.f;
}

// ---------------- x_proj GEMM: [16384,304] x [304,2048] + bias ----------------
// C[m][n], n: dir=n>>10, W row = n&1023 (PyTorch i,f,g,o stacking = g*256+u)
__global__ void k_gemm_xproj(const float* __restrict__ Wf, const float* __restrict__ Wb,
                             const float* __restrict__ bf, const float* __restrict__ bb) {
    __shared__ float As[16][68];
    __shared__ float Bs[16][68];
    int n0 = blockIdx.x * 64;
    int m0 = blockIdx.y * 64;
    int tid = threadIdx.x;
    int tm = tid >> 4, tn = tid & 15;
    int arow = tid >> 2, aq = tid & 3;

    int ng = n0 + arow;
    const float* Wrow = (ng < 1024) ? (Wf + (size_t)ng * EE) : (Wb + (size_t)(ng - 1024) * EE);

    float acc[4][4];
#pragma unroll
    for (int i = 0; i < 4; ++i)
#pragma unroll
        for (int j = 0; j < 4; ++j) acc[i][j] = 0.f;

    for (int kt = 0; kt < 19; ++kt) {
        int k0 = kt * 16;
        float4 av = *(const float4*)(g_emb + (size_t)(m0 + arow) * EP + k0 + aq * 4);
        As[aq * 4 + 0][arow] = av.x;
        As[aq * 4 + 1][arow] = av.y;
        As[aq * 4 + 2][arow] = av.z;
        As[aq * 4 + 3][arow] = av.w;
#pragma unroll
        for (int j = 0; j < 4; ++j) {
            int kk = k0 + aq * 4 + j;
            Bs[aq * 4 + j][arow] = (kk < EE) ? Wrow[kk] : 0.f;
        }
        __syncthreads();
#pragma unroll
        for (int k = 0; k < 16; ++k) {
            float4 a = *(const float4*)&As[k][tm * 4];
            float4 bq = *(const float4*)&Bs[k][tn * 4];
            acc[0][0] += a.x * bq.x; acc[0][1] += a.x * bq.y; acc[0][2] += a.x * bq.z; acc[0][3] += a.x * bq.w;
            acc[1][0] += a.y * bq.x; acc[1][1] += a.y * bq.y; acc[1][2] += a.y * bq.z; acc[1][3] += a.y * bq.w;
            acc[2][0] += a.z * bq.x; acc[2][1] += a.z * bq.y; acc[2][2] += a.z * bq.z; acc[2][3] += a.z * bq.w;
            acc[3][0] += a.w * bq.x; acc[3][1] += a.w * bq.y; acc[3][2] += a.w * bq.z; acc[3][3] += a.w * bq.w;
        }
        __syncthreads();
    }
    int nbase = n0 + tn * 4;
    float bias[4];
#pragma unroll
    for (int j = 0; j < 4; ++j) {
        int n = nbase + j;
        bias[j] = (n < 1024) ? bf[n] : bb[n - 1024];
    }
#pragma unroll
    for (int i = 0; i < 4; ++i) {
        int m = m0 + tm * 4 + i;
        float4 o;
        o.x = acc[i][0] + bias[0];
        o.y = acc[i][1] + bias[1];
        o.z = acc[i][2] + bias[2];
        o.w = acc[i][3] + bias[3];
        *(float4*)(g_xproj + (size_t)m * 2048 + nbase) = o;
    }
}

// ---------------- persistent BiLSTM recurrence ----------------
__device__ __forceinline__ void grid_barrier(unsigned* ls) {
    __syncthreads();
    if (threadIdx.x == 0) {
        *ls ^= 1u;
        __threadfence();
        unsigned old = atomicAdd(&g_cnt, 1u);
        if (old == NB_LSTM - 1) {
            g_cnt = 0u;
            __threadfence();
            atomicExch(&g_sense, *ls);
        } else {
            while (*(volatile unsigned*)&g_sense != *ls) { }
            __threadfence();
        }
    }
    __syncthreads();
}

__device__ __forceinline__ float sigf(float x) { return 1.f / (1.f + expf(-x)); }

// 128 blocks: dir(2) x unit-chunk(16, 16 units each) x batch-chunk(4, 16 rows each)
// thread (lu,lb): owns hidden unit U=uc*16+lu for batch b=bc*16+lb. c-state in register.
__global__ void __launch_bounds__(256, 1) k_lstm(const float* __restrict__ Whh_f,
                                                 const float* __restrict__ Whh_b) {
    extern __shared__ float sm[];
    float4* W4 = (float4*)sm;                 // [kc(64)][lu(16)][g(4)] = 64KB
    float4* h4 = (float4*)(sm + 16384);       // [kc(64)][lb(16)]       = 16KB

    int bx = blockIdx.x;
    int dir = bx >> 6;
    int rem = bx & 63;
    int uc = rem >> 2;
    int bc = rem & 3;
    int tid = threadIdx.x;
    int lu = tid >> 4;
    int lb = tid & 15;
    int U = uc * 16 + lu;
    int B0 = bc * 16;
    int b = B0 + lb;
    const float* Whh = dir ? Whh_b : Whh_f;

    // load W slice once: rows {g*256+U' : U' in chunk, g in 0..3}
    for (int i = tid; i < 64 * 64; i += 256) {
        int r = i >> 6;        // 0..63 local row
        int kc = i & 63;
        int lur = r >> 2, g = r & 3;
        int grow = g * 256 + uc * 16 + lur;
        W4[(kc * 16 + lur) * 4 + g] = *(const float4*)(Whh + (size_t)grow * HH + kc * 4);
    }

    float c_st = 0.f;
    unsigned ls = 0;

    for (int s = 0; s < TT; ++s) {
        int t = dir ? (TT - 1 - s) : s;
        float ai = 0.f, af = 0.f, ag = 0.f, ao = 0.f;
        if (s > 0) {
            grid_barrier(&ls);
            int tp = dir ? (t + 1) : (t - 1);
            const float* hp = g_hcat + ((size_t)(tp * 64 + B0)) * 512 + dir * 256;
#pragma unroll
            for (int i = 0; i < 4; ++i) {
                int idx = i * 256 + tid;
                int c4 = idx >> 4;
                int lbi = idx & 15;
                h4[c4 * 16 + lbi] = *(const float4*)(hp + lbi * 512 + c4 * 4);
            }
        }
        __syncthreads();
        if (s > 0) {
#pragma unroll 4
            for (int kc = 0; kc < 64; ++kc) {
                float4 hv = h4[kc * 16 + lb];
                const float4* wr = &W4[(kc * 16 + lu) * 4];
                float4 wi = wr[0], wf = wr[1], wg = wr[2], wo = wr[3];
                ai += hv.x * wi.x; ai += hv.y * wi.y; ai += hv.z * wi.z; ai += hv.w * wi.w;
                af += hv.x * wf.x; af += hv.y * wf.y; af += hv.z * wf.z; af += hv.w * wf.w;
                ag += hv.x * wg.x; ag += hv.y * wg.y; ag += hv.z * wg.z; ag += hv.w * wg.w;
                ao += hv.x * wo.x; ao += hv.y * wo.y; ao += hv.z * wo.z; ao += hv.w * wo.w;
            }
        }
        const float* xp = g_xproj + ((size_t)(t * 64 + b)) * 2048 + dir * 1024 + U;
        float pi = ai + xp[0];
        float pf = af + xp[256];
        float pg = ag + xp[512];
        float po = ao + xp[768];
        c_st = sigf(pf) * c_st + sigf(pi) * tanhf(pg);
        float h = sigf(po) * tanhf(c_st);
        g_hcat[((size_t)(t * 64 + b)) * 512 + dir * 256 + U] = h;
    }
    grid_barrier(&ls); // restore sense parity to 0 for next graph replay
}

// ---------------- fc1 + relu + cls -> unary (fused) ----------------
__global__ void k_fc(const float* __restrict__ W1, const float* __restrict__ b1,
                     const float* __restrict__ Wc, const float* __restrict__ bcls) {
    extern __shared__ float sm[];
    float (*As)[68]  = (float(*)[68])sm;                    // 16*68  = 1088 f
    float (*Bs)[132] = (float(*)[132])(sm + 1088);          // 16*132 = 2112 f
    float* cls_sh  = sm + 1088 + 2112;                      // 17*128 = 2176 f
    float* clsb_sh = cls_sh + 2176;                         // 32 f
    float* inter   = clsb_sh + 32;                          // 64*132 = 8448 f

    int m0 = blockIdx.x * 64;
    int tid = threadIdx.x;
    int tm = tid >> 4, tn = tid & 15;
    int arow = tid >> 2, aq = tid & 3;
    int brow = tid >> 1, bq = tid & 1;

    for (int i = tid; i < 17 * 128; i += 256) cls_sh[i] = Wc[i];
    if (tid < 17) clsb_sh[tid] = bcls[tid];

    float acc[4][8];
#pragma unroll
    for (int i = 0; i < 4; ++i)
#pragma unroll
        for (int j = 0; j < 8; ++j) acc[i][j] = 0.f;

    for (int kt = 0; kt < 32; ++kt) {
        int k0 = kt * 16;
        float4 av = *(const float4*)(g_hcat + (size_t)(m0 + arow) * 512 + k0 + aq * 4);
        As[aq * 4 + 0][arow] = av.x;
        As[aq * 4 + 1][arow] = av.y;
        As[aq * 4 + 2][arow] = av.z;
        As[aq * 4 + 3][arow] = av.w;
#pragma unroll
        for (int q = 0; q < 2; ++q) {
            float4 bv = *(const float4*)(W1 + (size_t)brow * 512 + k0 + bq * 8 + q * 4);
            Bs[bq * 8 + q * 4 + 0][brow] = bv.x;
            Bs[bq * 8 + q * 4 + 1][brow] = bv.y;
            Bs[bq * 8 + q * 4 + 2][brow] = bv.z;
            Bs[bq * 8 + q * 4 + 3][brow] = bv.w;
        }
        __syncthreads();
#pragma unroll
        for (int k = 0; k < 16; ++k) {
            float4 a  = *(const float4*)&As[k][tm * 4];
            float4 c0 = *(const float4*)&Bs[k][tn * 8];
            float4 c1 = *(const float4*)&Bs[k][tn * 8 + 4];
            float av4[4] = {a.x, a.y, a.z, a.w};
            float bv8[8] = {c0.x, c0.y, c0.z, c0.w, c1.x, c1.y, c1.z, c1.w};
#pragma unroll
            for (int i = 0; i < 4; ++i)
#pragma unroll
                for (int j = 0; j < 8; ++j) acc[i][j] += av4[i] * bv8[j];
        }
        __syncthreads();
    }
    // bias + relu -> inter smem
#pragma unroll
    for (int i = 0; i < 4; ++i) {
        int ml = tm * 4 + i;
#pragma unroll
        for (int j = 0; j < 8; ++j) {
            int n = tn * 8 + j;
            float v = acc[i][j] + b1[n];
            inter[ml * 132 + n] = v > 0.f ? v : 0.f;
        }
    }
    __syncthreads();
    // second GEMM: 64 x 17 (plus LOW_POT pad to 19)
    for (int o = tid; o < 64 * TL; o += 256) {
        int ml = o / TL, l = o - ml * TL;
        int m = m0 + ml;
        int t = m >> 6, bat = m & 63;
        float v;
        if (l < NUM_LABELS) {
            float s = clsb_sh[l];
            const float4* ip = (const float4*)(inter + ml * 132);
            const float4* cp = (const float4*)(cls_sh + l * 128);
#pragma unroll 8
            for (int k4 = 0; k4 < 32; ++k4) {
                float4 a = ip[k4], c = cp[k4];
                s += a.x * c.x + a.y * c.y + a.z * c.z + a.w * c.w;
            }
            v = s;
        } else {
            v = LOW_POT;
        }
        g_unary[((size_t)bat * TT + t) * TL + l] = v;
    }
}

// ---------------- Viterbi: one warp per batch element ----------------
__global__ void k_viterbi(const float* __restrict__ trans, float* __restrict__ out,
                          int score_off, int labels_off) {
    __shared__ float tr[TL * TL];
    __shared__ unsigned char bp[TT * TL];
    int b = blockIdx.x;
    int l = threadIdx.x;

    for (int i = l; i < TL * TL; i += 32) tr[i] = trans[i];
    __syncwarp();

    float score = (l == START_IDX) ? 0.f : LOW_POT;
    const float* ub = g_unary + (size_t)b * TT * TL;

    for (int t = 0; t < TT; ++t) {
        float u = (l < TL) ? ub[t * TL + l] : LOW_POT;
        float best = -3.4e38f;
        int bi = 0;
#pragma unroll
        for (int p = 0; p < TL; ++p) {
            float sp = __shfl_sync(0xffffffffu, score, p);
            float cnd = sp + ((l < TL) ? tr[l * TL + p] : 0.f);
            if (cnd > best) { best = cnd; bi = p; }   // strict > => first max (matches jnp.argmax)
        }
        score = best + u;
        if (l < TL) bp[t * TL + l] = (unsigned char)bi;
        __syncwarp();
    }
    float fin = (l < TL) ? (score + tr[END_IDX * TL + l]) : -3.4e38f;
    int idx = (l < TL) ? l : 31;
#pragma unroll
    for (int off = 16; off; off >>= 1) {
        float ov = __shfl_down_sync(0xffffffffu, fin, off);
        int   oi = __shfl_down_sync(0xffffffffu, idx, off);
        if (ov > fin || (ov == fin && oi < idx)) { fin = ov; idx = oi; }
    }
    if (l == 0) {
        if (score_off >= 0) out[score_off + b] = fin;
        if (labels_off >= 0) {
            int lab = idx;
            float* lo = out + labels_off + (size_t)b * TT;
            lo[TT - 1] = (float)lab;
            for (int t = TT - 1; t >= 1; --t) {
                lab = bp[t * TL + lab];
                lo[t - 1] = (float)lab;
            }
        }
    }
}

// ---------------- launch ----------------
extern "C" void kernel_launch(void* const* d_in, const int* in_sizes, int n_in,
                              void* d_out, int out_size) {
    const int*   x        = (const int*)d_in[0];
    const float* emb_tab  = (const float*)d_in[1];
    const float* W_ih_f   = (const float*)d_in[2];
    const float* W_hh_f   = (const float*)d_in[3];
    const float* b_f      = (const float*)d_in[4];
    const float* W_ih_b   = (const float*)d_in[5];
    const float* W_hh_b   = (const float*)d_in[6];
    const float* b_b      = (const float*)d_in[7];
    const float* fc1_W    = (const float*)d_in[8];
    const float* fc1_b    = (const float*)d_in[9];
    const float* cls_W    = (const float*)d_in[10];
    const float* cls_b    = (const float*)d_in[11];
    const float* trans    = (const float*)d_in[12];
    float* out = (float*)d_out;

    cudaFuncSetAttribute(k_lstm, cudaFuncAttributeMaxDynamicSharedMemorySize, 81920);
    cudaFuncSetAttribute(k_fc,   cudaFuncAttributeMaxDynamicSharedMemorySize, 57344);

    k_embed<<<(MTOT * EP + 255) / 256, 256>>>(x, emb_tab);

    dim3 g1(2048 / 64, MTOT / 64);
    k_gemm_xproj<<<g1, 256>>>(W_ih_f, W_ih_b, b_f, b_b);

    k_lstm<<<NB_LSTM, 256, 81920>>>(W_hh_f, W_hh_b);

    k_fc<<<MTOT / 64, 256, 57344>>>(fc1_W, fc1_b, cls_W, cls_b);

    int score_off, labels_off;
    if (out_size >= BB + BB * TT) { score_off = 0; labels_off = BB; }
    else if (out_size == BB * TT) { score_off = -1; labels_off = 0; }
    else                          { score_off = 0; labels_off = -1; }
    k_viterbi<<<BB, 32>>>(trans, out, score_off, labels_off);
}